// round 15
// baseline (speedup 1.0000x reference)
#include <cuda_runtime.h>
#include <cuda_fp16.h>
#include <math.h>
#include <stdint.h>

// Problem constants
#define B_   2
#define T_   2048
#define D_   1024
#define NH_  16
#define DH_  64
#define RTOT (B_*T_)          // 4096 rows
#define K_   D_               // GEMM K dim

// sqrt(0.125 * log2(e)) — applied to BOTH Q and K (balanced magnitudes).
#define QK_SCALE 0.42466089f
#define W_SCALE  64.0f        // weights pre-scaled into fp16 sweet spot

// ---------------------------------------------------------------------------
// Scratch (no cudaMalloc allowed). Everything single fp16.
// ---------------------------------------------------------------------------
__device__ __half g_X16[RTOT*D_];
__device__ __half g_Q16[RTOT*D_];
__device__ __half g_K16[RTOT*D_];
__device__ __half g_V16[RTOT*D_];
__device__ __half g_C[RTOT*D_];
__device__ __half g_WT[4][D_*D_];

// ---------------------------------------------------------------------------
// PTX helpers (standard PTX only)
// ---------------------------------------------------------------------------
__device__ __forceinline__ uint32_t smem_u32(const void* p) {
    uint32_t a;
    asm("{ .reg .u64 t; cvta.to.shared.u64 t, %1; cvt.u32.u64 %0, t; }"
        : "=r"(a) : "l"(p));
    return a;
}

#define CP_ASYNC16(dst, src) \
    asm volatile("cp.async.cg.shared.global [%0], [%1], 16;" \
                 :: "r"(dst), "l"(src))
#define CP_COMMIT() asm volatile("cp.async.commit_group;" ::: "memory")
#define CP_WAIT(n)  asm volatile("cp.async.wait_group %0;" :: "n"(n) : "memory")

__device__ __forceinline__ void ldsm4(uint32_t* r, uint32_t addr) {
    asm volatile("ldmatrix.sync.aligned.m8n8.x4.shared.b16 {%0,%1,%2,%3}, [%4];"
                 : "=r"(r[0]), "=r"(r[1]), "=r"(r[2]), "=r"(r[3]) : "r"(addr));
}
__device__ __forceinline__ void ldsm4t(uint32_t* r, uint32_t addr) {
    asm volatile("ldmatrix.sync.aligned.m8n8.x4.trans.shared.b16 {%0,%1,%2,%3}, [%4];"
                 : "=r"(r[0]), "=r"(r[1]), "=r"(r[2]), "=r"(r[3]) : "r"(addr));
}

__device__ __forceinline__ void mma_f16(float* d, const uint32_t* a,
                                        const uint32_t* b) {
    asm volatile(
        "mma.sync.aligned.m16n8k16.row.col.f32.f16.f16.f32 "
        "{%0,%1,%2,%3}, {%4,%5,%6,%7}, {%8,%9}, {%0,%1,%2,%3};"
        : "+f"(d[0]), "+f"(d[1]), "+f"(d[2]), "+f"(d[3])
        : "r"(a[0]), "r"(a[1]), "r"(a[2]), "r"(a[3]), "r"(b[0]), "r"(b[1]));
}

// fp16x2 exp2 (one MUFU op for two values); ex2(-inf) = 0
__device__ __forceinline__ uint32_t hex2(uint32_t x) {
    uint32_t r;
    asm("ex2.approx.f16x2 %0, %1;" : "=r"(r) : "r"(x));
    return r;
}

// pack: a -> low half, b -> high half
__device__ __forceinline__ uint32_t pack_f16x2(float a, float b) {
    uint32_t r;
    asm("cvt.rn.f16x2.f32 %0, %1, %2;" : "=r"(r) : "f"(b), "f"(a));
    return r;
}

// ---------------------------------------------------------------------------
// Convert x to single fp16
// ---------------------------------------------------------------------------
__global__ __launch_bounds__(256) void split_kernel(const float* __restrict__ src)
{
    int i = (blockIdx.x * 256 + threadIdx.x) * 4;
    float4 v = *(const float4*)(src + i);
    *(uint32_t*)(g_X16 + i)     = pack_f16x2(v.x, v.y);
    *(uint32_t*)(g_X16 + i + 2) = pack_f16x2(v.z, v.w);
}

// Transpose weights: W [K][N] fp32 -> [N][K] single fp16, x64 scale.
__global__ __launch_bounds__(256) void wtrans_kernel(const float* __restrict__ Wq,
                                                     const float* __restrict__ Wk,
                                                     const float* __restrict__ Wv,
                                                     const float* __restrict__ Wo)
{
    int z = blockIdx.z;
    const float* W = (z == 0) ? Wq : (z == 1) ? Wk : (z == 2) ? Wv : Wo;
    __half* Bt = g_WT[z];

    __shared__ float t[32][33];
    int n0 = blockIdx.x * 32, k0 = blockIdx.y * 32;
    for (int i = threadIdx.y; i < 32; i += 8)
        t[i][threadIdx.x] = W[(size_t)(k0 + i) * D_ + n0 + threadIdx.x];
    __syncthreads();
    for (int i = threadIdx.y; i < 32; i += 8)
        Bt[(size_t)(n0 + i) * D_ + k0 + threadIdx.x] =
            __float2half_rn(t[threadIdx.x][i] * W_SCALE);
}

// ---------------------------------------------------------------------------
// Single-pass fp16 GEMM via mma.sync: C = A @ B^T.
// Tile 128x128, BK=64 (stride-144 smem rows, conflict-free ldsm),
// 8 warps of 64x32, double-buffered cp.async.
// ---------------------------------------------------------------------------
#define SROWB   144                 // 64 fp16 = 128B + 16B pad
#define MAT_B   (128*SROWB)         // 18432
#define STAGE_G (2*MAT_B)           // 36864
#define GEMM_SMEM (2*STAGE_G)       // 73728
#define KITER   (K_/64)             // 16

#define GEMM_BODY(pA, pB)                                                     \
    _Pragma("unroll")                                                         \
    for (int ks = 0; ks < 4; ks++) {                                          \
        uint32_t ah[4][4];                                                    \
        const int akc = ks * 16 + (lane >> 4) * 8;                            \
        _Pragma("unroll")                                                     \
        for (int mb = 0; mb < 4; mb++) {                                      \
            uint32_t off = (uint32_t)(wm * 64 + mb * 16 + (lane & 15)) * SROWB\
                         + akc * 2;                                           \
            ldsm4(ah[mb], (pA) + off);                                        \
        }                                                                     \
        uint32_t bb[4][2];                                                    \
        const int brow = (lane & 7) + ((lane >> 4) & 1) * 8;                  \
        const int bkc  = ks * 16 + ((lane >> 3) & 1) * 8;                     \
        _Pragma("unroll")                                                     \
        for (int nb2 = 0; nb2 < 2; nb2++) {                                   \
            uint32_t off = (uint32_t)(wn * 32 + nb2 * 16 + brow) * SROWB      \
                         + bkc * 2;                                           \
            uint32_t t0[4];                                                   \
            ldsm4(t0, (pB) + off);                                            \
            bb[nb2*2][0] = t0[0]; bb[nb2*2][1] = t0[1];                       \
            bb[nb2*2+1][0] = t0[2]; bb[nb2*2+1][1] = t0[3];                   \
        }                                                                     \
        _Pragma("unroll")                                                     \
        for (int mb = 0; mb < 4; mb++)                                        \
            _Pragma("unroll")                                                 \
            for (int nb = 0; nb < 4; nb++)                                    \
                mma_f16(acc[mb][nb], ah[mb], bb[nb]);                         \
    }

#define GEMM_LOADER(Aptr, Bptr)                                               \
    auto load_stage = [&](int st, int k0) {                                   \
        uint32_t s0 = sb + st * STAGE_G;                                      \
        _Pragma("unroll")                                                     \
        for (int i = 0; i < 4; i++) {                                         \
            int c  = tid + i * 256;                                           \
            int r  = c >> 3;                                                  \
            int ch = c & 7;                                                   \
            uint32_t soff = r * SROWB + ch * 16;                              \
            CP_ASYNC16(s0 + soff,                                             \
                       (Aptr) + (size_t)(rowBase + r) * K_ + k0 + ch * 8);    \
            CP_ASYNC16(s0 + MAT_B + soff,                                     \
                       (Bptr) + (size_t)(colBase + r) * K_ + k0 + ch * 8);    \
        }                                                                     \
    };

#define GEMM_PIPELINE()                                                       \
    load_stage(0, 0);                                                         \
    CP_COMMIT();                                                              \
    for (int it = 0; it < KITER; it++) {                                      \
        if (it + 1 < KITER) {                                                 \
            load_stage((it + 1) & 1, (it + 1) * 64);                          \
            CP_COMMIT();                                                      \
            CP_WAIT(1);                                                       \
        } else {                                                              \
            CP_WAIT(0);                                                       \
        }                                                                     \
        __syncthreads();                                                      \
        uint32_t pA = sb + (it & 1) * STAGE_G;                                \
        uint32_t pB = pA + MAT_B;                                             \
        GEMM_BODY(pA, pB)                                                     \
        __syncthreads();                                                      \
    }

__global__ __launch_bounds__(256, 2) void gemm_kernel()
{
    extern __shared__ char sm[];
    const uint32_t sb = smem_u32(sm);
    const int tid  = threadIdx.x;
    const int wid  = tid >> 5;
    const int lane = tid & 31;
    const int wm   = wid & 1;
    const int wn   = wid >> 1;

    const int z = blockIdx.z;
    const __half* Bw = g_WT[z];
    __half* dst = (z == 0) ? g_Q16 : (z == 1) ? g_K16 : g_V16;
    const float scale = ((z == 2) ? 1.0f : QK_SCALE) / W_SCALE;

    const int rowBase = blockIdx.y * 128;
    const int colBase = blockIdx.x * 128;

    float acc[4][4][4];
#pragma unroll
    for (int i = 0; i < 4; i++)
#pragma unroll
        for (int j = 0; j < 4; j++)
#pragma unroll
            for (int e = 0; e < 4; e++) acc[i][j][e] = 0.0f;

    GEMM_LOADER(g_X16, Bw)
    GEMM_PIPELINE()

#pragma unroll
    for (int mb = 0; mb < 4; mb++) {
        int r0 = rowBase + wm * 64 + mb * 16 + (lane >> 2);
#pragma unroll
        for (int nb = 0; nb < 4; nb++) {
            int cc = colBase + wn * 32 + nb * 8 + (lane & 3) * 2;
            *(uint32_t*)(dst + (size_t)r0 * D_ + cc) =
                pack_f16x2(acc[mb][nb][0] * scale, acc[mb][nb][1] * scale);
            *(uint32_t*)(dst + (size_t)(r0 + 8) * D_ + cc) =
                pack_f16x2(acc[mb][nb][2] * scale, acc[mb][nb][3] * scale);
        }
    }
}

__global__ __launch_bounds__(256, 2) void outproj_kernel(float* __restrict__ out)
{
    extern __shared__ char sm[];
    const uint32_t sb = smem_u32(sm);
    const int tid  = threadIdx.x;
    const int wid  = tid >> 5;
    const int lane = tid & 31;
    const int wm   = wid & 1;
    const int wn   = wid >> 1;

    const int rowBase = blockIdx.y * 128;
    const int colBase = blockIdx.x * 128;

    float acc[4][4][4];
#pragma unroll
    for (int i = 0; i < 4; i++)
#pragma unroll
        for (int j = 0; j < 4; j++)
#pragma unroll
            for (int e = 0; e < 4; e++) acc[i][j][e] = 0.0f;

    GEMM_LOADER(g_C, g_WT[3])
    GEMM_PIPELINE()

    const float inv = 1.0f / W_SCALE;
#pragma unroll
    for (int mb = 0; mb < 4; mb++) {
        int r0 = rowBase + wm * 64 + mb * 16 + (lane >> 2);
#pragma unroll
        for (int nb = 0; nb < 4; nb++) {
            int cc = colBase + wn * 32 + nb * 8 + (lane & 3) * 2;
            *(float2*)(out + (size_t)r0 * D_ + cc) =
                make_float2(acc[mb][nb][0] * inv, acc[mb][nb][1] * inv);
            *(float2*)(out + (size_t)(r0 + 8) * D_ + cc) =
                make_float2(acc[mb][nb][2] * inv, acc[mb][nb][3] * inv);
        }
    }
}

// ---------------------------------------------------------------------------
// Flash attention (causal), all-single fp16 tensor cores. Block = 128 q-rows
// of one (b,h), 8 warps x 16 rows, 64-key tiles, double-buffered cp.async.
// No max subtraction (scores bounded). exp via ex2.approx.f16x2 (2/MUFU-op);
// row sums accumulated by an extra MMA against a ones fragment (fp32, exact).
// ---------------------------------------------------------------------------
#define AT_STRIDE 144               // 64 fp16 = 128B data + 16B pad
#define AT_SPLIT  (64*AT_STRIDE)    // 9216 per matrix
#define AT_STAGE  (2*AT_SPLIT)      // K + V = 18432
#define AT_SMEM   (2*AT_STAGE)      // 36864

__global__ __launch_bounds__(256, 2) void attn_kernel()
{
    extern __shared__ char sm[];
    const uint32_t sb = smem_u32(sm);
    const int tid  = threadIdx.x;
    const int w    = tid >> 5;
    const int lane = tid & 31;

    const int qt = (int)gridDim.x - 1 - (int)blockIdx.x;  // heavy blocks first
    const int h  = blockIdx.y;
    const int b  = blockIdx.z;
    const int qB = qt * 128;
    const size_t bhBase = (size_t)(b * T_) * D_ + h * 64;

    // ---- prologue: Q tile (single) -> smem -> register fragments ----
    {
#pragma unroll
        for (int i = 0; i < 4; i++) {
            int c = tid + i * 256;
            int r = c >> 3, ch = c & 7;
            const __half* src = g_Q16 + bhBase + (size_t)(qB + r) * D_ + ch * 8;
            CP_ASYNC16(sb + r * AT_STRIDE + ch * 16, src);
        }
        CP_COMMIT();
        CP_WAIT(0);
    }
    __syncthreads();

    uint32_t qq[4][4];
#pragma unroll
    for (int kc = 0; kc < 4; kc++) {
        uint32_t a = sb + (uint32_t)(w * 16 + (lane & 15)) * AT_STRIDE
                   + kc * 32 + (lane >> 4) * 16;
        ldsm4(qq[kc], a);
    }
    __syncthreads();   // Q consumed; smem reusable for K/V stages

    // ---- K/V stage loader ----
    auto load_kv = [&](int kt, int st) {
        uint32_t s0 = sb + st * AT_STAGE;
        int kB = kt * 64;
#pragma unroll
        for (int i = 0; i < 4; i++) {
            int c = tid + i * 256;
            int arr = c >> 9, rem = c & 511;
            int r = rem >> 3, ch = rem & 7;
            const __half* src = (arr == 0 ? g_K16 : g_V16)
                + bhBase + (size_t)(kB + r) * D_ + ch * 8;
            CP_ASYNC16(s0 + arr * AT_SPLIT + r * AT_STRIDE + ch * 16, src);
        }
    };

    float sO[8][4];
#pragma unroll
    for (int nb = 0; nb < 8; nb++)
#pragma unroll
        for (int e = 0; e < 4; e++) sO[nb][e] = 0.0f;
    float accL[4] = {0.0f, 0.0f, 0.0f, 0.0f};   // row-sum accumulator (MMA-fed)

    const uint32_t onesB[2] = {0x3C003C00u, 0x3C003C00u};  // fp16 ones

    const int nk = 2 * qt + 2;
    load_kv(0, 0);
    CP_COMMIT();

    const int g    = lane >> 3;
    const int l7   = lane & 7;
    const int rTop = qB + w * 16 + 15;

    for (int kt = 0; kt < nk; kt++) {
        const int st = kt & 1;
        if (kt + 1 < nk) {
            load_kv(kt + 1, st ^ 1);
            CP_COMMIT();
            CP_WAIT(1);
        } else {
            CP_WAIT(0);
        }
        __syncthreads();

        const int kB = kt * 64;
        const bool diag = (kt >= 2 * qt);

        if (!(diag && kB > rTop)) {
            const uint32_t pK = sb + st * AT_STAGE;
            const uint32_t pV = pK + AT_SPLIT;

            // ---- S = Q K^T (single pass) ----
            float sS[8][4];
#pragma unroll
            for (int nb = 0; nb < 8; nb++)
#pragma unroll
                for (int e = 0; e < 4; e++) sS[nb][e] = 0.0f;

#pragma unroll
            for (int kc = 0; kc < 4; kc++)
#pragma unroll
                for (int np = 0; np < 4; np++) {
                    uint32_t kk[4];
                    uint32_t ka = pK
                        + (uint32_t)(np * 16 + (g >> 1) * 8 + l7) * AT_STRIDE
                        + kc * 32 + (g & 1) * 16;
                    ldsm4(kk, ka);
                    mma_f16(sS[2*np],   qq[kc], kk);
                    mma_f16(sS[2*np+1], qq[kc], kk + 2);
                }

            // ---- causal mask ----
            if (diag) {
                const int r0 = qB + w * 16 + (lane >> 2);
#pragma unroll
                for (int nb = 0; nb < 8; nb++) {
                    int cb = kB + nb * 8 + (lane & 3) * 2;
                    if (cb     > r0)     sS[nb][0] = -INFINITY;
                    if (cb + 1 > r0)     sS[nb][1] = -INFINITY;
                    if (cb     > r0 + 8) sS[nb][2] = -INFINITY;
                    if (cb + 1 > r0 + 8) sS[nb][3] = -INFINITY;
                }
            }

            // ---- p = ex2(s) in fp16x2; row sums via ones-MMA; O += P V ----
#pragma unroll
            for (int kc = 0; kc < 4; kc++) {
                uint32_t ph[4];
                ph[0] = hex2(pack_f16x2(sS[2*kc][0],   sS[2*kc][1]));
                ph[1] = hex2(pack_f16x2(sS[2*kc][2],   sS[2*kc][3]));
                ph[2] = hex2(pack_f16x2(sS[2*kc+1][0], sS[2*kc+1][1]));
                ph[3] = hex2(pack_f16x2(sS[2*kc+1][2], sS[2*kc+1][3]));
                mma_f16(accL, ph, onesB);   // l += row-sum of these 16 keys
#pragma unroll
                for (int np = 0; np < 4; np++) {
                    uint32_t vv[4];
                    uint32_t va = pV
                        + (uint32_t)(kc * 16 + (g & 1) * 8 + l7) * AT_STRIDE
                        + np * 32 + (g >> 1) * 16;
                    ldsm4t(vv, va);
                    mma_f16(sO[2*np],   ph, vv);
                    mma_f16(sO[2*np+1], ph, vv + 2);
                }
            }
        }
        __syncthreads();
    }

    // ---- epilogue: normalize (accL[0]/[2] hold exact fp32 row sums) ----
    const float i0 = 1.0f / accL[0], i1 = 1.0f / accL[2];
    const size_t base0 = bhBase + (size_t)(qB + w * 16 + (lane >> 2)) * D_
                       + (lane & 3) * 2;
#pragma unroll
    for (int nb = 0; nb < 8; nb++) {
        *(uint32_t*)(g_C + base0 + nb * 8) =
            pack_f16x2(sO[nb][0] * i0, sO[nb][1] * i0);
        *(uint32_t*)(g_C + base0 + (size_t)8 * D_ + nb * 8) =
            pack_f16x2(sO[nb][2] * i1, sO[nb][3] * i1);
    }
}

// ---------------------------------------------------------------------------

extern "C" void kernel_launch(void* const* d_in, const int* in_sizes, int n_in,
                              void* d_out, int out_size)
{
    const float* x  = (const float*)d_in[0];
    const float* Wq = (const float*)d_in[1];
    const float* Wk = (const float*)d_in[2];
    const float* Wv = (const float*)d_in[3];
    const float* Wo = (const float*)d_in[4];
    float* out = (float*)d_out;

    cudaFuncSetAttribute(gemm_kernel, cudaFuncAttributeMaxDynamicSharedMemorySize,
                         GEMM_SMEM);
    cudaFuncSetAttribute(outproj_kernel, cudaFuncAttributeMaxDynamicSharedMemorySize,
                         GEMM_SMEM);
    cudaFuncSetAttribute(attn_kernel, cudaFuncAttributeMaxDynamicSharedMemorySize,
                         AT_SMEM);

    // x -> single fp16; 4 weights -> transposed single fp16 (x64)
    split_kernel<<<RTOT * D_ / 1024, 256>>>(x);
    wtrans_kernel<<<dim3(32, 32, 4), dim3(32, 8)>>>(Wq, Wk, Wv, Wo);

    // QKV projections (single-pass fp16, BK=64)
    gemm_kernel<<<dim3(D_ / 128, RTOT / 128, 3), 256, GEMM_SMEM>>>();

    // Causal flash attention (fp16, fp16x2 exp, MMA row sums)
    attn_kernel<<<dim3(T_ / 128, NH_, B_), 256, AT_SMEM>>>();

    // Output projection (single-pass fp16, BK=64) -> fp32 out
    outproj_kernel<<<dim3(D_ / 128, RTOT / 128), 256, GEMM_SMEM>>>(out);
}

// round 16
// speedup vs baseline: 1.5324x; 1.5324x over previous
#include <cuda_runtime.h>
#include <cuda_fp16.h>
#include <math.h>
#include <stdint.h>

// Problem constants
#define B_   2
#define T_   2048
#define D_   1024
#define NH_  16
#define DH_  64
#define RTOT (B_*T_)          // 4096 rows
#define K_   D_               // GEMM K dim

// sqrt(0.125 * log2(e)) — applied to BOTH Q and K (balanced magnitudes).
#define QK_SCALE 0.42466089f
#define W_SCALE  64.0f        // weights pre-scaled into fp16 sweet spot

// ---------------------------------------------------------------------------
// Scratch (no cudaMalloc allowed). Everything single fp16.
// ---------------------------------------------------------------------------
__device__ __half g_X16[RTOT*D_];
__device__ __half g_Q16[RTOT*D_];
__device__ __half g_K16[RTOT*D_];
__device__ __half g_V16[RTOT*D_];
__device__ __half g_C[RTOT*D_];
__device__ __half g_WT[4][D_*D_];

// ---------------------------------------------------------------------------
// PTX helpers (standard PTX only)
// ---------------------------------------------------------------------------
__device__ __forceinline__ uint32_t smem_u32(const void* p) {
    uint32_t a;
    asm("{ .reg .u64 t; cvta.to.shared.u64 t, %1; cvt.u32.u64 %0, t; }"
        : "=r"(a) : "l"(p));
    return a;
}

#define CP_ASYNC16(dst, src) \
    asm volatile("cp.async.cg.shared.global [%0], [%1], 16;" \
                 :: "r"(dst), "l"(src))
#define CP_COMMIT() asm volatile("cp.async.commit_group;" ::: "memory")
#define CP_WAIT(n)  asm volatile("cp.async.wait_group %0;" :: "n"(n) : "memory")

__device__ __forceinline__ void ldsm4(uint32_t* r, uint32_t addr) {
    asm volatile("ldmatrix.sync.aligned.m8n8.x4.shared.b16 {%0,%1,%2,%3}, [%4];"
                 : "=r"(r[0]), "=r"(r[1]), "=r"(r[2]), "=r"(r[3]) : "r"(addr));
}
__device__ __forceinline__ void ldsm4t(uint32_t* r, uint32_t addr) {
    asm volatile("ldmatrix.sync.aligned.m8n8.x4.trans.shared.b16 {%0,%1,%2,%3}, [%4];"
                 : "=r"(r[0]), "=r"(r[1]), "=r"(r[2]), "=r"(r[3]) : "r"(addr));
}

__device__ __forceinline__ void mma_f16(float* d, const uint32_t* a,
                                        const uint32_t* b) {
    asm volatile(
        "mma.sync.aligned.m16n8k16.row.col.f32.f16.f16.f32 "
        "{%0,%1,%2,%3}, {%4,%5,%6,%7}, {%8,%9}, {%0,%1,%2,%3};"
        : "+f"(d[0]), "+f"(d[1]), "+f"(d[2]), "+f"(d[3])
        : "r"(a[0]), "r"(a[1]), "r"(a[2]), "r"(a[3]), "r"(b[0]), "r"(b[1]));
}

// fp16x2 exp2 (one MUFU op for two values); ex2(-inf) = 0
__device__ __forceinline__ uint32_t hex2(uint32_t x) {
    uint32_t r;
    asm("ex2.approx.f16x2 %0, %1;" : "=r"(r) : "r"(x));
    return r;
}

// pack: a -> low half, b -> high half
__device__ __forceinline__ uint32_t pack_f16x2(float a, float b) {
    uint32_t r;
    asm("cvt.rn.f16x2.f32 %0, %1, %2;" : "=r"(r) : "f"(b), "f"(a));
    return r;
}

// ---------------------------------------------------------------------------
// Convert x to single fp16
// ---------------------------------------------------------------------------
__global__ __launch_bounds__(256) void split_kernel(const float* __restrict__ src)
{
    int i = (blockIdx.x * 256 + threadIdx.x) * 4;
    float4 v = *(const float4*)(src + i);
    *(uint32_t*)(g_X16 + i)     = pack_f16x2(v.x, v.y);
    *(uint32_t*)(g_X16 + i + 2) = pack_f16x2(v.z, v.w);
}

// Transpose weights: W [K][N] fp32 -> [N][K] single fp16, x64 scale.
__global__ __launch_bounds__(256) void wtrans_kernel(const float* __restrict__ Wq,
                                                     const float* __restrict__ Wk,
                                                     const float* __restrict__ Wv,
                                                     const float* __restrict__ Wo)
{
    int z = blockIdx.z;
    const float* W = (z == 0) ? Wq : (z == 1) ? Wk : (z == 2) ? Wv : Wo;
    __half* Bt = g_WT[z];

    __shared__ float t[32][33];
    int n0 = blockIdx.x * 32, k0 = blockIdx.y * 32;
    for (int i = threadIdx.y; i < 32; i += 8)
        t[i][threadIdx.x] = W[(size_t)(k0 + i) * D_ + n0 + threadIdx.x];
    __syncthreads();
    for (int i = threadIdx.y; i < 32; i += 8)
        Bt[(size_t)(n0 + i) * D_ + k0 + threadIdx.x] =
            __float2half_rn(t[threadIdx.x][i] * W_SCALE);
}

// ---------------------------------------------------------------------------
// Single-pass fp16 GEMM via mma.sync: C = A @ B^T.
// Tile 128x128, BK=64 (stride-144 smem rows, conflict-free ldsm),
// 8 warps of 64x32, double-buffered cp.async.
// ---------------------------------------------------------------------------
#define SROWB   144                 // 64 fp16 = 128B + 16B pad
#define MAT_B   (128*SROWB)         // 18432
#define STAGE_G (2*MAT_B)           // 36864
#define GEMM_SMEM (2*STAGE_G)       // 73728
#define KITER   (K_/64)             // 16

#define GEMM_BODY(pA, pB)                                                     \
    _Pragma("unroll")                                                         \
    for (int ks = 0; ks < 4; ks++) {                                          \
        uint32_t ah[4][4];                                                    \
        const int akc = ks * 16 + (lane >> 4) * 8;                            \
        _Pragma("unroll")                                                     \
        for (int mb = 0; mb < 4; mb++) {                                      \
            uint32_t off = (uint32_t)(wm * 64 + mb * 16 + (lane & 15)) * SROWB\
                         + akc * 2;                                           \
            ldsm4(ah[mb], (pA) + off);                                        \
        }                                                                     \
        uint32_t bb[4][2];                                                    \
        const int brow = (lane & 7) + ((lane >> 4) & 1) * 8;                  \
        const int bkc  = ks * 16 + ((lane >> 3) & 1) * 8;                     \
        _Pragma("unroll")                                                     \
        for (int nb2 = 0; nb2 < 2; nb2++) {                                   \
            uint32_t off = (uint32_t)(wn * 32 + nb2 * 16 + brow) * SROWB      \
                         + bkc * 2;                                           \
            uint32_t t0[4];                                                   \
            ldsm4(t0, (pB) + off);                                            \
            bb[nb2*2][0] = t0[0]; bb[nb2*2][1] = t0[1];                       \
            bb[nb2*2+1][0] = t0[2]; bb[nb2*2+1][1] = t0[3];                   \
        }                                                                     \
        _Pragma("unroll")                                                     \
        for (int mb = 0; mb < 4; mb++)                                        \
            _Pragma("unroll")                                                 \
            for (int nb = 0; nb < 4; nb++)                                    \
                mma_f16(acc[mb][nb], ah[mb], bb[nb]);                         \
    }

#define GEMM_LOADER(Aptr, Bptr)                                               \
    auto load_stage = [&](int st, int k0) {                                   \
        uint32_t s0 = sb + st * STAGE_G;                                      \
        _Pragma("unroll")                                                     \
        for (int i = 0; i < 4; i++) {                                         \
            int c  = tid + i * 256;                                           \
            int r  = c >> 3;                                                  \
            int ch = c & 7;                                                   \
            uint32_t soff = r * SROWB + ch * 16;                              \
            CP_ASYNC16(s0 + soff,                                             \
                       (Aptr) + (size_t)(rowBase + r) * K_ + k0 + ch * 8);    \
            CP_ASYNC16(s0 + MAT_B + soff,                                     \
                       (Bptr) + (size_t)(colBase + r) * K_ + k0 + ch * 8);    \
        }                                                                     \
    };

#define GEMM_PIPELINE()                                                       \
    load_stage(0, 0);                                                         \
    CP_COMMIT();                                                              \
    for (int it = 0; it < KITER; it++) {                                      \
        if (it + 1 < KITER) {                                                 \
            load_stage((it + 1) & 1, (it + 1) * 64);                          \
            CP_COMMIT();                                                      \
            CP_WAIT(1);                                                       \
        } else {                                                              \
            CP_WAIT(0);                                                       \
        }                                                                     \
        __syncthreads();                                                      \
        uint32_t pA = sb + (it & 1) * STAGE_G;                                \
        uint32_t pB = pA + MAT_B;                                             \
        GEMM_BODY(pA, pB)                                                     \
        __syncthreads();                                                      \
    }

__global__ __launch_bounds__(256, 2) void gemm_kernel()
{
    extern __shared__ char sm[];
    const uint32_t sb = smem_u32(sm);
    const int tid  = threadIdx.x;
    const int wid  = tid >> 5;
    const int lane = tid & 31;
    const int wm   = wid & 1;
    const int wn   = wid >> 1;

    const int z = blockIdx.z;
    const __half* Bw = g_WT[z];
    __half* dst = (z == 0) ? g_Q16 : (z == 1) ? g_K16 : g_V16;
    const float scale = ((z == 2) ? 1.0f : QK_SCALE) / W_SCALE;

    const int rowBase = blockIdx.y * 128;
    const int colBase = blockIdx.x * 128;

    float acc[4][4][4];
#pragma unroll
    for (int i = 0; i < 4; i++)
#pragma unroll
        for (int j = 0; j < 4; j++)
#pragma unroll
            for (int e = 0; e < 4; e++) acc[i][j][e] = 0.0f;

    GEMM_LOADER(g_X16, Bw)
    GEMM_PIPELINE()

#pragma unroll
    for (int mb = 0; mb < 4; mb++) {
        int r0 = rowBase + wm * 64 + mb * 16 + (lane >> 2);
#pragma unroll
        for (int nb = 0; nb < 4; nb++) {
            int cc = colBase + wn * 32 + nb * 8 + (lane & 3) * 2;
            *(uint32_t*)(dst + (size_t)r0 * D_ + cc) =
                pack_f16x2(acc[mb][nb][0] * scale, acc[mb][nb][1] * scale);
            *(uint32_t*)(dst + (size_t)(r0 + 8) * D_ + cc) =
                pack_f16x2(acc[mb][nb][2] * scale, acc[mb][nb][3] * scale);
        }
    }
}

__global__ __launch_bounds__(256, 2) void outproj_kernel(float* __restrict__ out)
{
    extern __shared__ char sm[];
    const uint32_t sb = smem_u32(sm);
    const int tid  = threadIdx.x;
    const int wid  = tid >> 5;
    const int lane = tid & 31;
    const int wm   = wid & 1;
    const int wn   = wid >> 1;

    const int rowBase = blockIdx.y * 128;
    const int colBase = blockIdx.x * 128;

    float acc[4][4][4];
#pragma unroll
    for (int i = 0; i < 4; i++)
#pragma unroll
        for (int j = 0; j < 4; j++)
#pragma unroll
            for (int e = 0; e < 4; e++) acc[i][j][e] = 0.0f;

    GEMM_LOADER(g_C, g_WT[3])
    GEMM_PIPELINE()

    const float inv = 1.0f / W_SCALE;
#pragma unroll
    for (int mb = 0; mb < 4; mb++) {
        int r0 = rowBase + wm * 64 + mb * 16 + (lane >> 2);
#pragma unroll
        for (int nb = 0; nb < 4; nb++) {
            int cc = colBase + wn * 32 + nb * 8 + (lane & 3) * 2;
            *(float2*)(out + (size_t)r0 * D_ + cc) =
                make_float2(acc[mb][nb][0] * inv, acc[mb][nb][1] * inv);
            *(float2*)(out + (size_t)(r0 + 8) * D_ + cc) =
                make_float2(acc[mb][nb][2] * inv, acc[mb][nb][3] * inv);
        }
    }
}

// ---------------------------------------------------------------------------
// Flash attention (causal), all-single fp16 tensor cores. Block = 128 q-rows
// of one (b,h), 8 warps x 16 rows, 64-key tiles, double-buffered cp.async.
// No max subtraction (scores bounded). exp via ex2.approx.f16x2 (2/MUFU-op);
// row sums accumulated by an extra MMA against a ones fragment (fp32, exact).
// ---------------------------------------------------------------------------
#define AT_STRIDE 144               // 64 fp16 = 128B data + 16B pad
#define AT_SPLIT  (64*AT_STRIDE)    // 9216 per matrix
#define AT_STAGE  (2*AT_SPLIT)      // K + V = 18432
#define AT_SMEM   (2*AT_STAGE)      // 36864

__global__ __launch_bounds__(256, 2) void attn_kernel()
{
    extern __shared__ char sm[];
    const uint32_t sb = smem_u32(sm);
    const int tid  = threadIdx.x;
    const int w    = tid >> 5;
    const int lane = tid & 31;

    const int qt = (int)gridDim.x - 1 - (int)blockIdx.x;  // heavy blocks first
    const int h  = blockIdx.y;
    const int b  = blockIdx.z;
    const int qB = qt * 128;
    const size_t bhBase = (size_t)(b * T_) * D_ + h * 64;

    // ---- prologue: Q tile (single) -> smem -> register fragments ----
    {
#pragma unroll
        for (int i = 0; i < 4; i++) {
            int c = tid + i * 256;
            int r = c >> 3, ch = c & 7;
            const __half* src = g_Q16 + bhBase + (size_t)(qB + r) * D_ + ch * 8;
            CP_ASYNC16(sb + r * AT_STRIDE + ch * 16, src);
        }
        CP_COMMIT();
        CP_WAIT(0);
    }
    __syncthreads();

    uint32_t qq[4][4];
#pragma unroll
    for (int kc = 0; kc < 4; kc++) {
        uint32_t a = sb + (uint32_t)(w * 16 + (lane & 15)) * AT_STRIDE
                   + kc * 32 + (lane >> 4) * 16;
        ldsm4(qq[kc], a);
    }
    __syncthreads();   // Q consumed; smem reusable for K/V stages

    // ---- K/V stage loader ----
    auto load_kv = [&](int kt, int st) {
        uint32_t s0 = sb + st * AT_STAGE;
        int kB = kt * 64;
#pragma unroll
        for (int i = 0; i < 4; i++) {
            int c = tid + i * 256;
            int arr = c >> 9, rem = c & 511;
            int r = rem >> 3, ch = rem & 7;
            const __half* src = (arr == 0 ? g_K16 : g_V16)
                + bhBase + (size_t)(kB + r) * D_ + ch * 8;
            CP_ASYNC16(s0 + arr * AT_SPLIT + r * AT_STRIDE + ch * 16, src);
        }
    };

    float sO[8][4];
#pragma unroll
    for (int nb = 0; nb < 8; nb++)
#pragma unroll
        for (int e = 0; e < 4; e++) sO[nb][e] = 0.0f;
    float accL[4] = {0.0f, 0.0f, 0.0f, 0.0f};   // row-sum accumulator (MMA-fed)

    const uint32_t onesB[2] = {0x3C003C00u, 0x3C003C00u};  // fp16 ones

    const int nk = 2 * qt + 2;
    load_kv(0, 0);
    CP_COMMIT();

    const int g    = lane >> 3;
    const int l7   = lane & 7;
    const int rTop = qB + w * 16 + 15;

    for (int kt = 0; kt < nk; kt++) {
        const int st = kt & 1;
        if (kt + 1 < nk) {
            load_kv(kt + 1, st ^ 1);
            CP_COMMIT();
            CP_WAIT(1);
        } else {
            CP_WAIT(0);
        }
        __syncthreads();

        const int kB = kt * 64;
        const bool diag = (kt >= 2 * qt);

        if (!(diag && kB > rTop)) {
            const uint32_t pK = sb + st * AT_STAGE;
            const uint32_t pV = pK + AT_SPLIT;

            // ---- S = Q K^T (single pass) ----
            float sS[8][4];
#pragma unroll
            for (int nb = 0; nb < 8; nb++)
#pragma unroll
                for (int e = 0; e < 4; e++) sS[nb][e] = 0.0f;

#pragma unroll
            for (int kc = 0; kc < 4; kc++)
#pragma unroll
                for (int np = 0; np < 4; np++) {
                    uint32_t kk[4];
                    uint32_t ka = pK
                        + (uint32_t)(np * 16 + (g >> 1) * 8 + l7) * AT_STRIDE
                        + kc * 32 + (g & 1) * 16;
                    ldsm4(kk, ka);
                    mma_f16(sS[2*np],   qq[kc], kk);
                    mma_f16(sS[2*np+1], qq[kc], kk + 2);
                }

            // ---- causal mask ----
            if (diag) {
                const int r0 = qB + w * 16 + (lane >> 2);
#pragma unroll
                for (int nb = 0; nb < 8; nb++) {
                    int cb = kB + nb * 8 + (lane & 3) * 2;
                    if (cb     > r0)     sS[nb][0] = -INFINITY;
                    if (cb + 1 > r0)     sS[nb][1] = -INFINITY;
                    if (cb     > r0 + 8) sS[nb][2] = -INFINITY;
                    if (cb + 1 > r0 + 8) sS[nb][3] = -INFINITY;
                }
            }

            // ---- p = ex2(s) in fp16x2; row sums via ones-MMA; O += P V ----
#pragma unroll
            for (int kc = 0; kc < 4; kc++) {
                uint32_t ph[4];
                ph[0] = hex2(pack_f16x2(sS[2*kc][0],   sS[2*kc][1]));
                ph[1] = hex2(pack_f16x2(sS[2*kc][2],   sS[2*kc][3]));
                ph[2] = hex2(pack_f16x2(sS[2*kc+1][0], sS[2*kc+1][1]));
                ph[3] = hex2(pack_f16x2(sS[2*kc+1][2], sS[2*kc+1][3]));
                mma_f16(accL, ph, onesB);   // l += row-sum of these 16 keys
#pragma unroll
                for (int np = 0; np < 4; np++) {
                    uint32_t vv[4];
                    uint32_t va = pV
                        + (uint32_t)(kc * 16 + (g & 1) * 8 + l7) * AT_STRIDE
                        + np * 32 + (g >> 1) * 16;
                    ldsm4t(vv, va);
                    mma_f16(sO[2*np],   ph, vv);
                    mma_f16(sO[2*np+1], ph, vv + 2);
                }
            }
        }
        __syncthreads();
    }

    // ---- epilogue: normalize (accL[0]/[2] hold exact fp32 row sums) ----
    const float i0 = 1.0f / accL[0], i1 = 1.0f / accL[2];
    const size_t base0 = bhBase + (size_t)(qB + w * 16 + (lane >> 2)) * D_
                       + (lane & 3) * 2;
#pragma unroll
    for (int nb = 0; nb < 8; nb++) {
        *(uint32_t*)(g_C + base0 + nb * 8) =
            pack_f16x2(sO[nb][0] * i0, sO[nb][1] * i0);
        *(uint32_t*)(g_C + base0 + (size_t)8 * D_ + nb * 8) =
            pack_f16x2(sO[nb][2] * i1, sO[nb][3] * i1);
    }
}

// ---------------------------------------------------------------------------

extern "C" void kernel_launch(void* const* d_in, const int* in_sizes, int n_in,
                              void* d_out, int out_size)
{
    const float* x  = (const float*)d_in[0];
    const float* Wq = (const float*)d_in[1];
    const float* Wk = (const float*)d_in[2];
    const float* Wv = (const float*)d_in[3];
    const float* Wo = (const float*)d_in[4];
    float* out = (float*)d_out;

    cudaFuncSetAttribute(gemm_kernel, cudaFuncAttributeMaxDynamicSharedMemorySize,
                         GEMM_SMEM);
    cudaFuncSetAttribute(outproj_kernel, cudaFuncAttributeMaxDynamicSharedMemorySize,
                         GEMM_SMEM);
    cudaFuncSetAttribute(attn_kernel, cudaFuncAttributeMaxDynamicSharedMemorySize,
                         AT_SMEM);

    // x -> single fp16; 4 weights -> transposed single fp16 (x64)
    split_kernel<<<RTOT * D_ / 1024, 256>>>(x);
    wtrans_kernel<<<dim3(32, 32, 4), dim3(32, 8)>>>(Wq, Wk, Wv, Wo);

    // QKV projections (single-pass fp16, BK=64)
    gemm_kernel<<<dim3(D_ / 128, RTOT / 128, 3), 256, GEMM_SMEM>>>();

    // Causal flash attention (fp16, fp16x2 exp, MMA row sums)
    attn_kernel<<<dim3(T_ / 128, NH_, B_), 256, AT_SMEM>>>();

    // Output projection (single-pass fp16, BK=64) -> fp32 out
    outproj_kernel<<<dim3(D_ / 128, RTOT / 128), 256, GEMM_SMEM>>>(out);
}

// round 17
// speedup vs baseline: 1.5343x; 1.0012x over previous
#include <cuda_runtime.h>
#include <cuda_fp16.h>
#include <math.h>
#include <stdint.h>

// Problem constants
#define B_   2
#define T_   2048
#define D_   1024
#define NH_  16
#define DH_  64
#define RTOT (B_*T_)          // 4096 rows
#define K_   D_               // GEMM K dim

// sqrt(0.125 * log2(e)) — applied to BOTH Q and K (balanced magnitudes).
#define QK_SCALE 0.42466089f
#define W_SCALE  64.0f        // weights pre-scaled into fp16 sweet spot

// ---------------------------------------------------------------------------
// Scratch (no cudaMalloc allowed). Everything single fp16.
// ---------------------------------------------------------------------------
__device__ __half g_X16[RTOT*D_];
__device__ __half g_Q16[RTOT*D_];
__device__ __half g_K16[RTOT*D_];
__device__ __half g_V16[RTOT*D_];
__device__ __half g_C[RTOT*D_];
__device__ __half g_WT[4][D_*D_];

// ---------------------------------------------------------------------------
// PTX helpers (standard PTX only)
// ---------------------------------------------------------------------------
__device__ __forceinline__ uint32_t smem_u32(const void* p) {
    uint32_t a;
    asm("{ .reg .u64 t; cvta.to.shared.u64 t, %1; cvt.u32.u64 %0, t; }"
        : "=r"(a) : "l"(p));
    return a;
}

#define CP_ASYNC16(dst, src) \
    asm volatile("cp.async.cg.shared.global [%0], [%1], 16;" \
                 :: "r"(dst), "l"(src))
#define CP_COMMIT() asm volatile("cp.async.commit_group;" ::: "memory")
#define CP_WAIT(n)  asm volatile("cp.async.wait_group %0;" :: "n"(n) : "memory")

__device__ __forceinline__ void ldsm4(uint32_t* r, uint32_t addr) {
    asm volatile("ldmatrix.sync.aligned.m8n8.x4.shared.b16 {%0,%1,%2,%3}, [%4];"
                 : "=r"(r[0]), "=r"(r[1]), "=r"(r[2]), "=r"(r[3]) : "r"(addr));
}
__device__ __forceinline__ void ldsm4t(uint32_t* r, uint32_t addr) {
    asm volatile("ldmatrix.sync.aligned.m8n8.x4.trans.shared.b16 {%0,%1,%2,%3}, [%4];"
                 : "=r"(r[0]), "=r"(r[1]), "=r"(r[2]), "=r"(r[3]) : "r"(addr));
}

__device__ __forceinline__ void mma_f16(float* d, const uint32_t* a,
                                        const uint32_t* b) {
    asm volatile(
        "mma.sync.aligned.m16n8k16.row.col.f32.f16.f16.f32 "
        "{%0,%1,%2,%3}, {%4,%5,%6,%7}, {%8,%9}, {%0,%1,%2,%3};"
        : "+f"(d[0]), "+f"(d[1]), "+f"(d[2]), "+f"(d[3])
        : "r"(a[0]), "r"(a[1]), "r"(a[2]), "r"(a[3]), "r"(b[0]), "r"(b[1]));
}

// fp16x2 exp2 (one MUFU op for two values); ex2(-inf) = 0
__device__ __forceinline__ uint32_t hex2(uint32_t x) {
    uint32_t r;
    asm("ex2.approx.f16x2 %0, %1;" : "=r"(r) : "r"(x));
    return r;
}

// pack: a -> low half, b -> high half
__device__ __forceinline__ uint32_t pack_f16x2(float a, float b) {
    uint32_t r;
    asm("cvt.rn.f16x2.f32 %0, %1, %2;" : "=r"(r) : "f"(b), "f"(a));
    return r;
}

// ---------------------------------------------------------------------------
// Convert x to single fp16
// ---------------------------------------------------------------------------
__global__ __launch_bounds__(256) void split_kernel(const float* __restrict__ src)
{
    int i = (blockIdx.x * 256 + threadIdx.x) * 4;
    float4 v = *(const float4*)(src + i);
    *(uint32_t*)(g_X16 + i)     = pack_f16x2(v.x, v.y);
    *(uint32_t*)(g_X16 + i + 2) = pack_f16x2(v.z, v.w);
}

// Transpose weights: W [K][N] fp32 -> [N][K] single fp16, x64 scale.
__global__ __launch_bounds__(256) void wtrans_kernel(const float* __restrict__ Wq,
                                                     const float* __restrict__ Wk,
                                                     const float* __restrict__ Wv,
                                                     const float* __restrict__ Wo)
{
    int z = blockIdx.z;
    const float* W = (z == 0) ? Wq : (z == 1) ? Wk : (z == 2) ? Wv : Wo;
    __half* Bt = g_WT[z];

    __shared__ float t[32][33];
    int n0 = blockIdx.x * 32, k0 = blockIdx.y * 32;
    for (int i = threadIdx.y; i < 32; i += 8)
        t[i][threadIdx.x] = W[(size_t)(k0 + i) * D_ + n0 + threadIdx.x];
    __syncthreads();
    for (int i = threadIdx.y; i < 32; i += 8)
        Bt[(size_t)(n0 + i) * D_ + k0 + threadIdx.x] =
            __float2half_rn(t[threadIdx.x][i] * W_SCALE);
}

// ---------------------------------------------------------------------------
// Single-pass fp16 GEMM via mma.sync: C = A @ B^T.
// Tile 128x128, BK=64 (stride-144 smem rows, conflict-free ldsm),
// 8 warps of 64x32, double-buffered cp.async.
// ---------------------------------------------------------------------------
#define SROWB   144                 // 64 fp16 = 128B + 16B pad
#define MAT_B   (128*SROWB)         // 18432
#define STAGE_G (2*MAT_B)           // 36864
#define GEMM_SMEM (2*STAGE_G)       // 73728
#define KITER   (K_/64)             // 16

#define GEMM_BODY(pA, pB)                                                     \
    _Pragma("unroll")                                                         \
    for (int ks = 0; ks < 4; ks++) {                                          \
        uint32_t ah[4][4];                                                    \
        const int akc = ks * 16 + (lane >> 4) * 8;                            \
        _Pragma("unroll")                                                     \
        for (int mb = 0; mb < 4; mb++) {                                      \
            uint32_t off = (uint32_t)(wm * 64 + mb * 16 + (lane & 15)) * SROWB\
                         + akc * 2;                                           \
            ldsm4(ah[mb], (pA) + off);                                        \
        }                                                                     \
        uint32_t bb[4][2];                                                    \
        const int brow = (lane & 7) + ((lane >> 4) & 1) * 8;                  \
        const int bkc  = ks * 16 + ((lane >> 3) & 1) * 8;                     \
        _Pragma("unroll")                                                     \
        for (int nb2 = 0; nb2 < 2; nb2++) {                                   \
            uint32_t off = (uint32_t)(wn * 32 + nb2 * 16 + brow) * SROWB      \
                         + bkc * 2;                                           \
            uint32_t t0[4];                                                   \
            ldsm4(t0, (pB) + off);                                            \
            bb[nb2*2][0] = t0[0]; bb[nb2*2][1] = t0[1];                       \
            bb[nb2*2+1][0] = t0[2]; bb[nb2*2+1][1] = t0[3];                   \
        }                                                                     \
        _Pragma("unroll")                                                     \
        for (int mb = 0; mb < 4; mb++)                                        \
            _Pragma("unroll")                                                 \
            for (int nb = 0; nb < 4; nb++)                                    \
                mma_f16(acc[mb][nb], ah[mb], bb[nb]);                         \
    }

#define GEMM_LOADER(Aptr, Bptr)                                               \
    auto load_stage = [&](int st, int k0) {                                   \
        uint32_t s0 = sb + st * STAGE_G;                                      \
        _Pragma("unroll")                                                     \
        for (int i = 0; i < 4; i++) {                                         \
            int c  = tid + i * 256;                                           \
            int r  = c >> 3;                                                  \
            int ch = c & 7;                                                   \
            uint32_t soff = r * SROWB + ch * 16;                              \
            CP_ASYNC16(s0 + soff,                                             \
                       (Aptr) + (size_t)(rowBase + r) * K_ + k0 + ch * 8);    \
            CP_ASYNC16(s0 + MAT_B + soff,                                     \
                       (Bptr) + (size_t)(colBase + r) * K_ + k0 + ch * 8);    \
        }                                                                     \
    };

#define GEMM_PIPELINE()                                                       \
    load_stage(0, 0);                                                         \
    CP_COMMIT();                                                              \
    for (int it = 0; it < KITER; it++) {                                      \
        if (it + 1 < KITER) {                                                 \
            load_stage((it + 1) & 1, (it + 1) * 64);                          \
            CP_COMMIT();                                                      \
            CP_WAIT(1);                                                       \
        } else {                                                              \
            CP_WAIT(0);                                                       \
        }                                                                     \
        __syncthreads();                                                      \
        uint32_t pA = sb + (it & 1) * STAGE_G;                                \
        uint32_t pB = pA + MAT_B;                                             \
        GEMM_BODY(pA, pB)                                                     \
        __syncthreads();                                                      \
    }

__global__ __launch_bounds__(256, 2) void gemm_kernel()
{
    extern __shared__ char sm[];
    const uint32_t sb = smem_u32(sm);
    const int tid  = threadIdx.x;
    const int wid  = tid >> 5;
    const int lane = tid & 31;
    const int wm   = wid & 1;
    const int wn   = wid >> 1;

    const int z = blockIdx.z;
    const __half* Bw = g_WT[z];
    __half* dst = (z == 0) ? g_Q16 : (z == 1) ? g_K16 : g_V16;
    const float scale = ((z == 2) ? 1.0f : QK_SCALE) / W_SCALE;

    const int rowBase = blockIdx.y * 128;
    const int colBase = blockIdx.x * 128;

    float acc[4][4][4];
#pragma unroll
    for (int i = 0; i < 4; i++)
#pragma unroll
        for (int j = 0; j < 4; j++)
#pragma unroll
            for (int e = 0; e < 4; e++) acc[i][j][e] = 0.0f;

    GEMM_LOADER(g_X16, Bw)
    GEMM_PIPELINE()

#pragma unroll
    for (int mb = 0; mb < 4; mb++) {
        int r0 = rowBase + wm * 64 + mb * 16 + (lane >> 2);
#pragma unroll
        for (int nb = 0; nb < 4; nb++) {
            int cc = colBase + wn * 32 + nb * 8 + (lane & 3) * 2;
            *(uint32_t*)(dst + (size_t)r0 * D_ + cc) =
                pack_f16x2(acc[mb][nb][0] * scale, acc[mb][nb][1] * scale);
            *(uint32_t*)(dst + (size_t)(r0 + 8) * D_ + cc) =
                pack_f16x2(acc[mb][nb][2] * scale, acc[mb][nb][3] * scale);
        }
    }
}

__global__ __launch_bounds__(256, 2) void outproj_kernel(float* __restrict__ out)
{
    extern __shared__ char sm[];
    const uint32_t sb = smem_u32(sm);
    const int tid  = threadIdx.x;
    const int wid  = tid >> 5;
    const int lane = tid & 31;
    const int wm   = wid & 1;
    const int wn   = wid >> 1;

    const int rowBase = blockIdx.y * 128;
    const int colBase = blockIdx.x * 128;

    float acc[4][4][4];
#pragma unroll
    for (int i = 0; i < 4; i++)
#pragma unroll
        for (int j = 0; j < 4; j++)
#pragma unroll
            for (int e = 0; e < 4; e++) acc[i][j][e] = 0.0f;

    GEMM_LOADER(g_C, g_WT[3])
    GEMM_PIPELINE()

    const float inv = 1.0f / W_SCALE;
#pragma unroll
    for (int mb = 0; mb < 4; mb++) {
        int r0 = rowBase + wm * 64 + mb * 16 + (lane >> 2);
#pragma unroll
        for (int nb = 0; nb < 4; nb++) {
            int cc = colBase + wn * 32 + nb * 8 + (lane & 3) * 2;
            *(float2*)(out + (size_t)r0 * D_ + cc) =
                make_float2(acc[mb][nb][0] * inv, acc[mb][nb][1] * inv);
            *(float2*)(out + (size_t)(r0 + 8) * D_ + cc) =
                make_float2(acc[mb][nb][2] * inv, acc[mb][nb][3] * inv);
        }
    }
}

// ---------------------------------------------------------------------------
// Flash attention (causal), all-single fp16 tensor cores. Block = 128 q-rows
// of one (b,h), 8 warps x 16 rows, 64-key tiles, double-buffered cp.async.
// No max subtraction (scores bounded). exp via ex2.approx.f16x2 (2/MUFU-op);
// row sums accumulated by an extra MMA against a ones fragment (fp32, exact).
// ---------------------------------------------------------------------------
#define AT_STRIDE 144               // 64 fp16 = 128B data + 16B pad
#define AT_SPLIT  (64*AT_STRIDE)    // 9216 per matrix
#define AT_STAGE  (2*AT_SPLIT)      // K + V = 18432
#define AT_SMEM   (2*AT_STAGE)      // 36864

__global__ __launch_bounds__(256, 2) void attn_kernel()
{
    extern __shared__ char sm[];
    const uint32_t sb = smem_u32(sm);
    const int tid  = threadIdx.x;
    const int w    = tid >> 5;
    const int lane = tid & 31;

    const int qt = (int)gridDim.x - 1 - (int)blockIdx.x;  // heavy blocks first
    const int h  = blockIdx.y;
    const int b  = blockIdx.z;
    const int qB = qt * 128;
    const size_t bhBase = (size_t)(b * T_) * D_ + h * 64;

    // ---- prologue: Q tile (single) -> smem -> register fragments ----
    {
#pragma unroll
        for (int i = 0; i < 4; i++) {
            int c = tid + i * 256;
            int r = c >> 3, ch = c & 7;
            const __half* src = g_Q16 + bhBase + (size_t)(qB + r) * D_ + ch * 8;
            CP_ASYNC16(sb + r * AT_STRIDE + ch * 16, src);
        }
        CP_COMMIT();
        CP_WAIT(0);
    }
    __syncthreads();

    uint32_t qq[4][4];
#pragma unroll
    for (int kc = 0; kc < 4; kc++) {
        uint32_t a = sb + (uint32_t)(w * 16 + (lane & 15)) * AT_STRIDE
                   + kc * 32 + (lane >> 4) * 16;
        ldsm4(qq[kc], a);
    }
    __syncthreads();   // Q consumed; smem reusable for K/V stages

    // ---- K/V stage loader ----
    auto load_kv = [&](int kt, int st) {
        uint32_t s0 = sb + st * AT_STAGE;
        int kB = kt * 64;
#pragma unroll
        for (int i = 0; i < 4; i++) {
            int c = tid + i * 256;
            int arr = c >> 9, rem = c & 511;
            int r = rem >> 3, ch = rem & 7;
            const __half* src = (arr == 0 ? g_K16 : g_V16)
                + bhBase + (size_t)(kB + r) * D_ + ch * 8;
            CP_ASYNC16(s0 + arr * AT_SPLIT + r * AT_STRIDE + ch * 16, src);
        }
    };

    float sO[8][4];
#pragma unroll
    for (int nb = 0; nb < 8; nb++)
#pragma unroll
        for (int e = 0; e < 4; e++) sO[nb][e] = 0.0f;
    float accL[4] = {0.0f, 0.0f, 0.0f, 0.0f};   // row-sum accumulator (MMA-fed)

    const uint32_t onesB[2] = {0x3C003C00u, 0x3C003C00u};  // fp16 ones

    const int nk = 2 * qt + 2;
    load_kv(0, 0);
    CP_COMMIT();

    const int g    = lane >> 3;
    const int l7   = lane & 7;
    const int rTop = qB + w * 16 + 15;

    for (int kt = 0; kt < nk; kt++) {
        const int st = kt & 1;
        if (kt + 1 < nk) {
            load_kv(kt + 1, st ^ 1);
            CP_COMMIT();
            CP_WAIT(1);
        } else {
            CP_WAIT(0);
        }
        __syncthreads();

        const int kB = kt * 64;
        const bool diag = (kt >= 2 * qt);

        if (!(diag && kB > rTop)) {
            const uint32_t pK = sb + st * AT_STAGE;
            const uint32_t pV = pK + AT_SPLIT;

            // ---- S = Q K^T (single pass) ----
            float sS[8][4];
#pragma unroll
            for (int nb = 0; nb < 8; nb++)
#pragma unroll
                for (int e = 0; e < 4; e++) sS[nb][e] = 0.0f;

#pragma unroll
            for (int kc = 0; kc < 4; kc++)
#pragma unroll
                for (int np = 0; np < 4; np++) {
                    uint32_t kk[4];
                    uint32_t ka = pK
                        + (uint32_t)(np * 16 + (g >> 1) * 8 + l7) * AT_STRIDE
                        + kc * 32 + (g & 1) * 16;
                    ldsm4(kk, ka);
                    mma_f16(sS[2*np],   qq[kc], kk);
                    mma_f16(sS[2*np+1], qq[kc], kk + 2);
                }

            // ---- causal mask ----
            if (diag) {
                const int r0 = qB + w * 16 + (lane >> 2);
#pragma unroll
                for (int nb = 0; nb < 8; nb++) {
                    int cb = kB + nb * 8 + (lane & 3) * 2;
                    if (cb     > r0)     sS[nb][0] = -INFINITY;
                    if (cb + 1 > r0)     sS[nb][1] = -INFINITY;
                    if (cb     > r0 + 8) sS[nb][2] = -INFINITY;
                    if (cb + 1 > r0 + 8) sS[nb][3] = -INFINITY;
                }
            }

            // ---- p = ex2(s) in fp16x2; row sums via ones-MMA; O += P V ----
#pragma unroll
            for (int kc = 0; kc < 4; kc++) {
                uint32_t ph[4];
                ph[0] = hex2(pack_f16x2(sS[2*kc][0],   sS[2*kc][1]));
                ph[1] = hex2(pack_f16x2(sS[2*kc][2],   sS[2*kc][3]));
                ph[2] = hex2(pack_f16x2(sS[2*kc+1][0], sS[2*kc+1][1]));
                ph[3] = hex2(pack_f16x2(sS[2*kc+1][2], sS[2*kc+1][3]));
                mma_f16(accL, ph, onesB);   // l += row-sum of these 16 keys
#pragma unroll
                for (int np = 0; np < 4; np++) {
                    uint32_t vv[4];
                    uint32_t va = pV
                        + (uint32_t)(kc * 16 + (g & 1) * 8 + l7) * AT_STRIDE
                        + np * 32 + (g >> 1) * 16;
                    ldsm4t(vv, va);
                    mma_f16(sO[2*np],   ph, vv);
                    mma_f16(sO[2*np+1], ph, vv + 2);
                }
            }
        }
        __syncthreads();
    }

    // ---- epilogue: normalize (accL[0]/[2] hold exact fp32 row sums) ----
    const float i0 = 1.0f / accL[0], i1 = 1.0f / accL[2];
    const size_t base0 = bhBase + (size_t)(qB + w * 16 + (lane >> 2)) * D_
                       + (lane & 3) * 2;
#pragma unroll
    for (int nb = 0; nb < 8; nb++) {
        *(uint32_t*)(g_C + base0 + nb * 8) =
            pack_f16x2(sO[nb][0] * i0, sO[nb][1] * i0);
        *(uint32_t*)(g_C + base0 + (size_t)8 * D_ + nb * 8) =
            pack_f16x2(sO[nb][2] * i1, sO[nb][3] * i1);
    }
}

// ---------------------------------------------------------------------------

extern "C" void kernel_launch(void* const* d_in, const int* in_sizes, int n_in,
                              void* d_out, int out_size)
{
    const float* x  = (const float*)d_in[0];
    const float* Wq = (const float*)d_in[1];
    const float* Wk = (const float*)d_in[2];
    const float* Wv = (const float*)d_in[3];
    const float* Wo = (const float*)d_in[4];
    float* out = (float*)d_out;

    cudaFuncSetAttribute(gemm_kernel, cudaFuncAttributeMaxDynamicSharedMemorySize,
                         GEMM_SMEM);
    cudaFuncSetAttribute(outproj_kernel, cudaFuncAttributeMaxDynamicSharedMemorySize,
                         GEMM_SMEM);
    cudaFuncSetAttribute(attn_kernel, cudaFuncAttributeMaxDynamicSharedMemorySize,
                         AT_SMEM);

    // x -> single fp16; 4 weights -> transposed single fp16 (x64)
    split_kernel<<<RTOT * D_ / 1024, 256>>>(x);
    wtrans_kernel<<<dim3(32, 32, 4), dim3(32, 8)>>>(Wq, Wk, Wv, Wo);

    // QKV projections (single-pass fp16, BK=64)
    gemm_kernel<<<dim3(D_ / 128, RTOT / 128, 3), 256, GEMM_SMEM>>>();

    // Causal flash attention (fp16, fp16x2 exp, MMA row sums)
    attn_kernel<<<dim3(T_ / 128, NH_, B_), 256, AT_SMEM>>>();

    // Output projection (single-pass fp16, BK=64) -> fp32 out
    outproj_kernel<<<dim3(D_ / 128, RTOT / 128), 256, GEMM_SMEM>>>(out);
}